// round 4
// baseline (speedup 1.0000x reference)
#include <cuda_runtime.h>
#include <cstdint>

// Problem constants
#define BATCH 64
#define TT    1000
#define NINP  64
#define HID   512
#define NACT  2

// Recurrence decomposition
#define CNC  8                    // CTAs per cluster (W_hh split 8 ways by column)
#define NB   4                    // batches per cluster
#define JPC  64                   // HID / CNC columns per CTA
#define NCLUSTER (BATCH / NB)     // 16 clusters -> 128 CTAs

// d_out layout: [out | hn_last | rnn_out]
#define HN_OFF  (BATCH * TT * NACT)
#define RNN_OFF (HN_OFF + BATCH * HID)

typedef unsigned long long u64;
typedef unsigned int u32;

// ---- packed f32x2 helpers ----
__device__ __forceinline__ u64 pk(float lo, float hi) {
    u64 r; asm("mov.b64 %0, {%1, %2};" : "=l"(r) : "f"(lo), "f"(hi)); return r;
}
__device__ __forceinline__ void upk(u64 v, float& lo, float& hi) {
    asm("mov.b64 {%0, %1}, %2;" : "=f"(lo), "=f"(hi) : "l"(v));
}
__device__ __forceinline__ u64 f2fma(u64 a, u64 b, u64 c) {
    u64 d; asm("fma.rn.f32x2 %0, %1, %2, %3;" : "=l"(d) : "l"(a), "l"(b), "l"(c));
    return d;
}

// ---- mbarrier helpers ----
#define MBINIT(addr, cnt) \
    asm volatile("mbarrier.init.shared.b64 [%0], %1;" :: "r"(addr), "r"(cnt) : "memory")
#define MB_EXPECT(addr, tx) \
    asm volatile("mbarrier.arrive.expect_tx.shared.b64 _, [%0], %1;" :: "r"(addr), "r"(tx) : "memory")
// CTA-scope acquire: data is tx-completed into OUR smem (TMA-multicast precedent);
// cluster-scope acquire would emit CCTL.IVALL (L1D flush) every step.
#define WAITC(addr, ph) \
    asm volatile("{\n\t.reg .pred P;\n\tWL%=:\n\t" \
                 "mbarrier.try_wait.parity.acquire.cta.shared::cta.b64 P, [%0], %1, 0x989680;\n\t" \
                 "@!P bra WL%=;\n\t}" :: "r"(addr), "r"(ph) : "memory")

// ---------------------------------------------------------------------------
// Kernel A: inp_proj[b,t,:] = inp[b,t,:] @ W_ih  (into rnn region, in-place)
// 4 tiles of 32 rows per block -> W_ih (128KB) reused from L1 after tile 0.
// ---------------------------------------------------------------------------
__global__ void __launch_bounds__(512, 1) k_inproj(
    const float* __restrict__ inp, const float* __restrict__ W_ih,
    float* __restrict__ rnn)
{
    __shared__ alignas(16) float2 xsp[16][NINP];   // [row_pair][k]

#pragma unroll 1
    for (int tile = 0; tile < 4; tile++) {
        const int row0 = (blockIdx.x * 4 + tile) * 32;
        __syncthreads();   // previous tile's xsp reads complete
        for (int i = threadIdx.x; i < 32 * NINP; i += 512) {
            const int r = i >> 6, k = i & 63;
            ((float*)&xsp[r >> 1][k])[r & 1] = inp[(size_t)(row0 + r) * NINP + k];
        }
        __syncthreads();

        const int j = threadIdx.x;
        u64 acc[16];
#pragma unroll
        for (int r2 = 0; r2 < 16; r2++) acc[r2] = 0ull;

#pragma unroll 8
        for (int k = 0; k < NINP; k += 2) {
            const float wa = W_ih[k * HID + j];
            const float wb = W_ih[(k + 1) * HID + j];
            const u64 w0 = pk(wa, wa), w1 = pk(wb, wb);
#pragma unroll
            for (int r2 = 0; r2 < 16; r2++) {
                const ulonglong2 hv = *reinterpret_cast<const ulonglong2*>(&xsp[r2][k]);
                acc[r2] = f2fma(hv.x, w0, acc[r2]);
                acc[r2] = f2fma(hv.y, w1, acc[r2]);
            }
        }
#pragma unroll
        for (int r2 = 0; r2 < 16; r2++) {
            float lo, hi; upk(acc[r2], lo, hi);
            rnn[(size_t)(row0 + 2 * r2) * HID + j]     = lo;
            rnn[(size_t)(row0 + 2 * r2 + 1) * HID + j] = hi;
        }
    }
}

// ---------------------------------------------------------------------------
// Kernel B: persistent clustered recurrence.
// h state in k-permuted layout h_perm[buf][src_rank*256 + b*64 + jj]
// (logical k = src_rank*64 + jj). Per-source-rank tx barriers: thread (kg)
// waits only for the two rank-blocks it consumes; own-rank block needs no
// barrier (guarded by the staging __syncthreads of the previous step).
// ---------------------------------------------------------------------------
__global__ void __cluster_dims__(CNC, 1, 1) __launch_bounds__(256, 1)
k_rnn(const float* __restrict__ hn, const float* __restrict__ W_hh,
      float* __restrict__ rnn, float* __restrict__ hn_last)
{
    __shared__ alignas(16) float h_perm[2][CNC * NB * JPC];  // 2 x 8KB
    __shared__ alignas(16) float red[4][NB][JPC];            // 4KB
    __shared__ alignas(8)  u64   mb[2][CNC];                 // [buf][src rank]

    u32 rank; asm("mov.u32 %0, %%cluster_ctarank;" : "=r"(rank));
    const int rank_i = (int)rank;
    const int cid    = blockIdx.x / CNC;
    const int b_base = cid * NB;

    const int tid = threadIdx.x;
    const int j   = tid & 63;     // local column (also epilogue jj)
    const int kg  = tid >> 6;     // k-quarter 0..3 (also epilogue batch)
    const int col = rank_i * JPC + j;
    const int gb  = b_base + kg;  // epilogue batch (global)

    // Weights: thread covers permuted rank-blocks rb = 2kg, 2kg+1.
    // w2[r2*32 + q] = (W_hh[k][col], W_hh[k+1][col]),  k = (2kg+r2)*64 + 2q
    u64 w2[64];
#pragma unroll
    for (int r2 = 0; r2 < 2; r2++)
#pragma unroll
        for (int q = 0; q < 32; q++) {
            const int k = (2 * kg + r2) * 64 + 2 * q;
            w2[r2 * 32 + q] =
                pk(W_hh[(size_t)k * HID + col], W_hh[(size_t)(k + 1) * HID + col]);
        }

    // Prefill h_perm[0] with h0
    for (int i = tid; i < CNC * NB * JPC; i += 256) {
        const int r = i >> 8, b = (i >> 6) & 3, jj = i & 63;
        h_perm[0][i] = hn[(size_t)(b_base + b) * HID + r * JPC + jj];
    }

    const u32 mb_base = (u32)__cvta_generic_to_shared(&mb[0][0]);
    if (tid < 2 * CNC) MBINIT(mb_base + (u32)tid * 8, 1);
    __syncthreads();
    asm volatile("barrier.cluster.arrive.aligned;\n\t"
                 "barrier.cluster.wait.aligned;" ::: "memory");

    // Remote bases in every cluster CTA
    const u32 hl = (u32)__cvta_generic_to_shared(&h_perm[0][0]);
    u32 rh[CNC], rm[CNC];
#pragma unroll
    for (int p = 0; p < CNC; p++) {
        asm("mapa.shared::cluster.u32 %0, %1, %2;" : "=r"(rh[p]) : "r"(hl), "r"(p));
        asm("mapa.shared::cluster.u32 %0, %1, %2;" : "=r"(rm[p]) : "r"(mb_base), "r"(p));
    }
    const u32 blk_off   = (u32)rank * (NB * JPC * 4);   // our 1KB block
    const u32 buf_bytes = CNC * NB * JPC * 4;           // 8KB per buffer

    // this thread's two rank-blocks; process own-rank one first (no wait)
    const int rb0 = 2 * kg, rb1 = 2 * kg + 1;
    const int first = (rb1 == rank_i) ? 1 : 0;

#pragma unroll 1
    for (int t = 0; t < TT; t++) {
        const int cur = t & 1, nxt = cur ^ 1;
        const u32 wp = (u32)(((t - 1) >> 1) & 1);        // wait phase (t>=1)
        const size_t xoff = ((size_t)gb * TT + t) * HID + col;
        const float xv = __ldg(&rnn[xoff]);              // prefetch before waits

        // post expects for NEXT buffer's incoming blocks (7 threads in parallel)
        if (t < TT - 1 && tid < CNC - 1) {
            const int r = tid + (tid >= rank_i);
            MB_EXPECT(mb_base + (u32)(nxt * CNC + r) * 8, NB * JPC * 4);
        }

        const float* hc = &h_perm[cur][0];
        u64 a0 = 0ull, a1 = 0ull, a2 = 0ull, a3 = 0ull;
#pragma unroll
        for (int s = 0; s < 2; s++) {
            const int r2 = first ^ s;
            const int rb = 2 * kg + r2;
            if (t > 0 && rb != rank_i)
                WAITC(mb_base + (u32)(cur * CNC + rb) * 8, wp);
            const ulonglong2* hp = (const ulonglong2*)(hc + rb * 256);
            const u64* wv = &w2[r2 * 32];
#pragma unroll
            for (int q = 0; q < 16; q++) {
                const u64 wlo = wv[2 * q], whi = wv[2 * q + 1];
                const ulonglong2 v0 = hp[0 * 16 + q];
                a0 = f2fma(v0.x, wlo, a0); a0 = f2fma(v0.y, whi, a0);
                const ulonglong2 v1 = hp[1 * 16 + q];
                a1 = f2fma(v1.x, wlo, a1); a1 = f2fma(v1.y, whi, a1);
                const ulonglong2 v2 = hp[2 * 16 + q];
                a2 = f2fma(v2.x, wlo, a2); a2 = f2fma(v2.y, whi, a2);
                const ulonglong2 v3 = hp[3 * 16 + q];
                a3 = f2fma(v3.x, wlo, a3); a3 = f2fma(v3.y, whi, a3);
            }
        }
        {
            float lo, hi;
            upk(a0, lo, hi); red[kg][0][j] = lo + hi;
            upk(a1, lo, hi); red[kg][1][j] = lo + hi;
            upk(a2, lo, hi); red[kg][2][j] = lo + hi;
            upk(a3, lo, hi); red[kg][3][j] = lo + hi;
        }
        __syncthreads();   // red[] ready (and all reads of h_perm[cur] done)

        // epilogue: thread -> (batch kg, column col)
        float v = red[0][kg][j] + red[1][kg][j] + red[2][kg][j] + red[3][kg][j] + xv;
        const float hval = 1.f / (1.f + __expf(-v));
        rnn[xoff] = hval;

        if (t < TT - 1) {
            // stage into our own block of the next buffer (this IS the self-copy)
            h_perm[nxt][rank_i * 256 + kg * 64 + j] = hval;
            __syncthreads();          // staging complete (also guards own-block reads at t+1)
            if (tid == 0) {
                asm volatile("fence.proxy.async.shared::cta;" ::: "memory");
                const u32 src = hl + (u32)nxt * buf_bytes + blk_off;
#pragma unroll
                for (int p = 0; p < CNC; p++) {
                    if (p == rank_i) continue;
                    const u32 dst  = rh[p] + (u32)nxt * buf_bytes + blk_off;
                    const u32 rbar = rm[p] + (u32)(nxt * CNC + rank_i) * 8;
                    asm volatile(
                        "cp.async.bulk.shared::cluster.shared::cta."
                        "mbarrier::complete_tx::bytes [%0], [%1], %2, [%3];"
                        :: "r"(dst), "r"(src), "r"(NB * JPC * 4), "r"(rbar) : "memory");
                }
            }
        } else {
            hn_last[(size_t)gb * HID + col] = hval;
        }
    }
}

// ---------------------------------------------------------------------------
// Kernel C: out = sigmoid(rnn_out @ W_fc + b_fc). One warp per (b,t) row.
// ---------------------------------------------------------------------------
__global__ void __launch_bounds__(256, 8) k_fc(
    const float* __restrict__ rnn, const float* __restrict__ W_fc,
    const float* __restrict__ b_fc, float* __restrict__ out)
{
    __shared__ float wfc[HID * NACT];
    for (int i = threadIdx.x; i < HID * NACT; i += 256) wfc[i] = W_fc[i];
    __syncthreads();

    const int warp = threadIdx.x >> 5, lane = threadIdx.x & 31;
    const size_t row = (size_t)blockIdx.x * 8 + warp;
    const float4* rp = reinterpret_cast<const float4*>(rnn + row * HID);

    float a0 = 0.f, a1 = 0.f;
#pragma unroll
    for (int i = 0; i < 4; i++) {
        const float4 vv = rp[lane + 32 * i];
        const int k = (lane + 32 * i) * 4;
        a0 = fmaf(vv.x, wfc[(k + 0) * 2 + 0], a0);
        a1 = fmaf(vv.x, wfc[(k + 0) * 2 + 1], a1);
        a0 = fmaf(vv.y, wfc[(k + 1) * 2 + 0], a0);
        a1 = fmaf(vv.y, wfc[(k + 1) * 2 + 1], a1);
        a0 = fmaf(vv.z, wfc[(k + 2) * 2 + 0], a0);
        a1 = fmaf(vv.z, wfc[(k + 2) * 2 + 1], a1);
        a0 = fmaf(vv.w, wfc[(k + 3) * 2 + 0], a0);
        a1 = fmaf(vv.w, wfc[(k + 3) * 2 + 1], a1);
    }
#pragma unroll
    for (int off = 16; off > 0; off >>= 1) {
        a0 += __shfl_xor_sync(0xffffffffu, a0, off);
        a1 += __shfl_xor_sync(0xffffffffu, a1, off);
    }
    if (lane == 0) {
        out[row * NACT + 0] = 1.f / (1.f + __expf(-(a0 + b_fc[0])));
        out[row * NACT + 1] = 1.f / (1.f + __expf(-(a1 + b_fc[1])));
    }
}

// ---------------------------------------------------------------------------
extern "C" void kernel_launch(void* const* d_in, const int* in_sizes, int n_in,
                              void* d_out, int out_size)
{
    const float* inp  = (const float*)d_in[0];
    const float* hn   = (const float*)d_in[1];
    const float* W_hh = (const float*)d_in[2];
    const float* W_ih = (const float*)d_in[3];
    const float* W_fc = (const float*)d_in[4];
    const float* b_fc = (const float*)d_in[5];

    float* out = (float*)d_out;
    float* hnl = out + HN_OFF;
    float* rnn = out + RNN_OFF;

    k_inproj<<<(BATCH * TT) / 128, 512>>>(inp, W_ih, rnn);
    k_rnn<<<NCLUSTER * CNC, 256>>>(hn, W_hh, rnn, hnl);
    k_fc<<<(BATCH * TT) / 8, 256>>>(rnn, W_fc, b_fc, out);
}

// round 5
// speedup vs baseline: 1.0257x; 1.0257x over previous
#include <cuda_runtime.h>
#include <cstdint>

// Problem constants
#define BATCH 64
#define TT    1000
#define NINP  64
#define HID   512
#define NACT  2

// Recurrence decomposition
#define CNC  8                    // CTAs per cluster (W_hh split by column)
#define NG   2                    // batch groups (software pipeline stages)
#define NB   4                    // batches per cluster
#define JPC  64                   // HID / CNC columns per CTA
#define NCLUSTER (BATCH / NB)     // 16 clusters -> 128 CTAs

#define BLK_F      128            // floats per exchange block (2 batches x 64 cols)
#define BLK_STRIDE 132            // padded stride (bank-conflict-free kg streams)
#define GBUF_F     (CNC * BLK_STRIDE)   // 1056 floats per (group, buffer)

// d_out layout: [out | hn_last | rnn_out]
#define HN_OFF  (BATCH * TT * NACT)
#define RNN_OFF (HN_OFF + BATCH * HID)

typedef unsigned long long u64;
typedef unsigned int u32;

// ---- packed f32x2 helpers ----
__device__ __forceinline__ u64 pk(float lo, float hi) {
    u64 r; asm("mov.b64 %0, {%1, %2};" : "=l"(r) : "f"(lo), "f"(hi)); return r;
}
__device__ __forceinline__ void upk(u64 v, float& lo, float& hi) {
    asm("mov.b64 {%0, %1}, %2;" : "=f"(lo), "=f"(hi) : "l"(v));
}
__device__ __forceinline__ u64 f2fma(u64 a, u64 b, u64 c) {
    u64 d; asm("fma.rn.f32x2 %0, %1, %2, %3;" : "=l"(d) : "l"(a), "l"(b), "l"(c));
    return d;
}

// ---- mbarrier helpers ----
#define MBINIT(addr, cnt) \
    asm volatile("mbarrier.init.shared.b64 [%0], %1;" :: "r"(addr), "r"(cnt) : "memory")
#define MB_EXPECT(addr, tx) \
    asm volatile("mbarrier.arrive.expect_tx.shared.b64 _, [%0], %1;" :: "r"(addr), "r"(tx) : "memory")
#define WAITC(addr, ph) \
    asm volatile("{\n\t.reg .pred P;\n\tWL%=:\n\t" \
                 "mbarrier.try_wait.parity.acquire.cta.shared::cta.b64 P, [%0], %1, 0x989680;\n\t" \
                 "@!P bra WL%=;\n\t}" :: "r"(addr), "r"(ph) : "memory")

// ---------------------------------------------------------------------------
// Dummy no-op kernel (shifts ncu's captured launch index onto k_rnn)
// ---------------------------------------------------------------------------
__global__ void k_nop() {}

// ---------------------------------------------------------------------------
// Kernel A: inp_proj[b,t,:] = inp[b,t,:] @ W_ih  (into rnn region, in-place)
// (R2 version — fastest measured variant)
// ---------------------------------------------------------------------------
__global__ void __launch_bounds__(512, 1) k_inproj(
    const float* __restrict__ inp, const float* __restrict__ W_ih,
    float* __restrict__ rnn)
{
    __shared__ alignas(16) float2 xsp[16][NINP];   // [row_pair][k]
    const int row0 = blockIdx.x * 32;
    for (int i = threadIdx.x; i < 32 * NINP; i += 512) {
        const int r = i >> 6, k = i & 63;
        ((float*)&xsp[r >> 1][k])[r & 1] = inp[(size_t)(row0 + r) * NINP + k];
    }
    __syncthreads();

    const int j = threadIdx.x;
    u64 acc[16];
#pragma unroll
    for (int r2 = 0; r2 < 16; r2++) acc[r2] = 0ull;

#pragma unroll 8
    for (int k = 0; k < NINP; k += 2) {
        const float wa = W_ih[k * HID + j];
        const float wb = W_ih[(k + 1) * HID + j];
        const u64 w0 = pk(wa, wa), w1 = pk(wb, wb);
#pragma unroll
        for (int r2 = 0; r2 < 16; r2++) {
            const ulonglong2 hv = *reinterpret_cast<const ulonglong2*>(&xsp[r2][k]);
            acc[r2] = f2fma(hv.x, w0, acc[r2]);
            acc[r2] = f2fma(hv.y, w1, acc[r2]);
        }
    }
#pragma unroll
    for (int r2 = 0; r2 < 16; r2++) {
        float lo, hi; upk(acc[r2], lo, hi);
        rnn[(size_t)(row0 + 2 * r2) * HID + j]     = lo;
        rnn[(size_t)(row0 + 2 * r2 + 1) * HID + j] = hi;
    }
}

// ---------------------------------------------------------------------------
// Kernel B: persistent clustered recurrence, 2-group software pipeline.
// Lane map: kg = lane>>3 (k-quarter), j = warp*8 + (lane&7) (column).
// h state per group in k-permuted, padded layout:
//   hbuf[g][buf][rb*132 + b*64 + jj],  logical k = rb*64 + jj, b in {0,1}.
// Reduction over kg via 2 butterfly shuffles (no barriers). Exchange = one
// 512B cp.async.bulk per peer per group, tx onto mb[g][buf].
// ---------------------------------------------------------------------------
__global__ void __cluster_dims__(CNC, 1, 1) __launch_bounds__(256, 1)
k_rnn(const float* __restrict__ hn, const float* __restrict__ W_hh,
      float* __restrict__ rnn, float* __restrict__ hn_last)
{
    __shared__ alignas(16) float hbuf[NG][2][GBUF_F];   // ~16.5 KB
    __shared__ alignas(8)  u64   mb[NG][2];             // full barriers

    u32 rank; asm("mov.u32 %0, %%cluster_ctarank;" : "=r"(rank));
    const int rank_i = (int)rank;
    const int cid    = blockIdx.x / CNC;
    const int b_base = cid * NB;

    const int tid = threadIdx.x;
    const int w   = tid >> 5, l = tid & 31;
    const int kg  = l >> 3;          // k-quarter 0..3
    const int j   = w * 8 + (l & 7); // column 0..63
    const int col = rank_i * JPC + j;
    const int bq  = kg & 1;          // staging batch-in-group (valid for kg<2)

    // Weights: k-quarter kg -> permuted rank-blocks rb = 2kg, 2kg+1
    u64 w2[64];
#pragma unroll
    for (int r2 = 0; r2 < 2; r2++)
#pragma unroll
        for (int q = 0; q < 32; q++) {
            const int k = (2 * kg + r2) * 64 + 2 * q;
            w2[r2 * 32 + q] =
                pk(W_hh[(size_t)k * HID + col], W_hh[(size_t)(k + 1) * HID + col]);
        }

    // Prefill both groups' buffer 0 with h0
    for (int i = tid; i < NG * GBUF_F; i += 256) {
        const int g = i / GBUF_F, r = i % GBUF_F;
        const int rb = r / BLK_STRIDE, o = r % BLK_STRIDE;
        if (o < BLK_F) {
            const int b = o >> 6, jj = o & 63;
            hbuf[g][0][rb * BLK_STRIDE + o] =
                hn[(size_t)(b_base + g * 2 + b) * HID + rb * 64 + jj];
        }
    }

    const u32 mb_base = (u32)__cvta_generic_to_shared(&mb[0][0]);
    if (tid < NG * 2) MBINIT(mb_base + (u32)tid * 8, 1);
    __syncthreads();
    asm volatile("barrier.cluster.arrive.aligned;\n\t"
                 "barrier.cluster.wait.aligned;" ::: "memory");

    const u32 hl = (u32)__cvta_generic_to_shared(&hbuf[0][0][0]);
    u32 rh[CNC], rm[CNC];
#pragma unroll
    for (int p = 0; p < CNC; p++) {
        asm("mapa.shared::cluster.u32 %0, %1, %2;" : "=r"(rh[p]) : "r"(hl), "r"(p));
        asm("mapa.shared::cluster.u32 %0, %1, %2;" : "=r"(rm[p]) : "r"(mb_base), "r"(p));
    }

    // Per-thread x/h gmem pointers (batch = g*2 + bq), advanced 512 floats/step
    float* xq0 = rnn + (size_t)(b_base + 0 + bq) * TT * HID + col;
    float* xq1 = rnn + (size_t)(b_base + 2 + bq) * TT * HID + col;

#pragma unroll 1
    for (int t = 0; t < TT; t++) {
        const int cur = t & 1, nxt = cur ^ 1, m = t >> 1;
        const u32 wp = (u32)((cur ? m : (m + 1)) & 1);
        const float xv0 = __ldg(xq0);
        const float xv1 = __ldg(xq1);

        if (tid == 0 && t < TT - 1) {
            MB_EXPECT(mb_base + (u32)(0 * 2 + nxt) * 8, (CNC - 1) * BLK_F * 4);
            MB_EXPECT(mb_base + (u32)(1 * 2 + nxt) * 8, (CNC - 1) * BLK_F * 4);
        }

#pragma unroll
        for (int g = 0; g < NG; g++) {
            if (t > 0) WAITC(mb_base + (u32)(g * 2 + cur) * 8, wp);

            const float* hc = &hbuf[g][cur][0];
            u64 A0 = 0ull, A1 = 0ull;
#pragma unroll
            for (int r2 = 0; r2 < 2; r2++) {
                const float* hp = hc + (2 * kg + r2) * BLK_STRIDE;
                const u64* wv = &w2[r2 * 32];
#pragma unroll
                for (int q = 0; q < 16; q++) {
                    const ulonglong2 v0 =
                        *reinterpret_cast<const ulonglong2*>(hp + 4 * q);
                    A0 = f2fma(v0.x, wv[2 * q], A0);
                    A0 = f2fma(v0.y, wv[2 * q + 1], A0);
                    const ulonglong2 v1 =
                        *reinterpret_cast<const ulonglong2*>(hp + 64 + 4 * q);
                    A1 = f2fma(v1.x, wv[2 * q], A1);
                    A1 = f2fma(v1.y, wv[2 * q + 1], A1);
                }
            }
            // horizontal + butterfly over kg (lane bits 3,4); no barriers
            float lo, hi, s0, s1;
            upk(A0, lo, hi); s0 = lo + hi;
            upk(A1, lo, hi); s1 = lo + hi;
            s0 += __shfl_xor_sync(0xffffffffu, s0, 8);
            s0 += __shfl_xor_sync(0xffffffffu, s0, 16);
            s1 += __shfl_xor_sync(0xffffffffu, s1, 8);
            s1 += __shfl_xor_sync(0xffffffffu, s1, 16);

            const float xv = g ? xv1 : xv0;
            const float s  = bq ? s1 : s0;
            const float hval = 1.f / (1.f + __expf(-(s + xv)));

            if (kg < 2) {   // staging lanes: batch = g*2 + kg
                if (g) *xq1 = hval; else *xq0 = hval;        // rnn_out
                hbuf[g][nxt][rank_i * BLK_STRIDE + kg * 64 + j] = hval;
                if (t == TT - 1)
                    hn_last[(size_t)(b_base + g * 2 + kg) * HID + col] = hval;
            }

            if (t < TT - 1) {
                __syncthreads();   // staging complete; prior reads of buf[nxt] done
                if (tid == 0) {
                    asm volatile("fence.proxy.async.shared::cta;" ::: "memory");
                    const u32 off = (u32)(((g * 2 + nxt) * GBUF_F +
                                           rank_i * BLK_STRIDE) * 4);
                    const u32 src = hl + off;
#pragma unroll
                    for (int p = 0; p < CNC; p++) {
                        if (p == rank_i) continue;
                        asm volatile(
                            "cp.async.bulk.shared::cluster.shared::cta."
                            "mbarrier::complete_tx::bytes [%0], [%1], %2, [%3];"
                            :: "r"(rh[p] + off), "r"(src), "r"(BLK_F * 4),
                               "r"(rm[p] + (u32)((g * 2 + nxt) * 8)) : "memory");
                    }
                }
            }
        }
        xq0 += HID; xq1 += HID;
    }
}

// ---------------------------------------------------------------------------
// Kernel C: out = sigmoid(rnn_out @ W_fc + b_fc). One warp per (b,t) row.
// ---------------------------------------------------------------------------
__global__ void __launch_bounds__(256, 8) k_fc(
    const float* __restrict__ rnn, const float* __restrict__ W_fc,
    const float* __restrict__ b_fc, float* __restrict__ out)
{
    __shared__ float wfc[HID * NACT];
    for (int i = threadIdx.x; i < HID * NACT; i += 256) wfc[i] = W_fc[i];
    __syncthreads();

    const int warp = threadIdx.x >> 5, lane = threadIdx.x & 31;
    const size_t row = (size_t)blockIdx.x * 8 + warp;
    const float4* rp = reinterpret_cast<const float4*>(rnn + row * HID);

    float a0 = 0.f, a1 = 0.f;
#pragma unroll
    for (int i = 0; i < 4; i++) {
        const float4 vv = rp[lane + 32 * i];
        const int k = (lane + 32 * i) * 4;
        a0 = fmaf(vv.x, wfc[(k + 0) * 2 + 0], a0);
        a1 = fmaf(vv.x, wfc[(k + 0) * 2 + 1], a1);
        a0 = fmaf(vv.y, wfc[(k + 1) * 2 + 0], a0);
        a1 = fmaf(vv.y, wfc[(k + 1) * 2 + 1], a1);
        a0 = fmaf(vv.z, wfc[(k + 2) * 2 + 0], a0);
        a1 = fmaf(vv.z, wfc[(k + 2) * 2 + 1], a1);
        a0 = fmaf(vv.w, wfc[(k + 3) * 2 + 0], a0);
        a1 = fmaf(vv.w, wfc[(k + 3) * 2 + 1], a1);
    }
#pragma unroll
    for (int off = 16; off > 0; off >>= 1) {
        a0 += __shfl_xor_sync(0xffffffffu, a0, off);
        a1 += __shfl_xor_sync(0xffffffffu, a1, off);
    }
    if (lane == 0) {
        out[row * NACT + 0] = 1.f / (1.f + __expf(-(a0 + b_fc[0])));
        out[row * NACT + 1] = 1.f / (1.f + __expf(-(a1 + b_fc[1])));
    }
}

// ---------------------------------------------------------------------------
extern "C" void kernel_launch(void* const* d_in, const int* in_sizes, int n_in,
                              void* d_out, int out_size)
{
    const float* inp  = (const float*)d_in[0];
    const float* hn   = (const float*)d_in[1];
    const float* W_hh = (const float*)d_in[2];
    const float* W_ih = (const float*)d_in[3];
    const float* W_fc = (const float*)d_in[4];
    const float* b_fc = (const float*)d_in[5];

    float* out = (float*)d_out;
    float* hnl = out + HN_OFF;
    float* rnn = out + RNN_OFF;

    k_inproj<<<(BATCH * TT) / 32, 512>>>(inp, W_ih, rnn);
    k_nop<<<1, 32>>>();   // shift ncu capture index onto k_rnn
    k_nop<<<1, 32>>>();
    k_rnn<<<NCLUSTER * CNC, 256>>>(hn, W_hh, rnn, hnl);
    k_fc<<<(BATCH * TT) / 8, 256>>>(rnn, W_fc, b_fc, out);
}

// round 6
// speedup vs baseline: 1.3801x; 1.3455x over previous
#include <cuda_runtime.h>
#include <cstdint>

// Problem constants
#define BATCH 64
#define TT    1000
#define NINP  64
#define HID   512
#define NACT  2

// Recurrence decomposition
#define CNC  8                    // CTAs per cluster (W_hh split by column)
#define NB   4                    // batches per cluster
#define JPC  64                   // HID / CNC columns per CTA
#define NCLUSTER (BATCH / NB)     // 16 clusters -> 128 CTAs

// d_out layout: [out | hn_last | rnn_out]
#define HN_OFF  (BATCH * TT * NACT)
#define RNN_OFF (HN_OFF + BATCH * HID)

typedef unsigned long long u64;
typedef unsigned int u32;

// ---- packed f32x2 helpers ----
__device__ __forceinline__ u64 pk(float lo, float hi) {
    u64 r; asm("mov.b64 %0, {%1, %2};" : "=l"(r) : "f"(lo), "f"(hi)); return r;
}
__device__ __forceinline__ void upk(u64 v, float& lo, float& hi) {
    asm("mov.b64 {%0, %1}, %2;" : "=f"(lo), "=f"(hi) : "l"(v));
}
__device__ __forceinline__ u64 f2fma(u64 a, u64 b, u64 c) {
    u64 d; asm("fma.rn.f32x2 %0, %1, %2, %3;" : "=l"(d) : "l"(a), "l"(b), "l"(c));
    return d;
}

// ---- mbarrier helpers ----
#define MBINIT(addr, cnt) \
    asm volatile("mbarrier.init.shared.b64 [%0], %1;" :: "r"(addr), "r"(cnt) : "memory")
#define MB_EXPECT(addr, tx) \
    asm volatile("mbarrier.arrive.expect_tx.shared.b64 _, [%0], %1;" :: "r"(addr), "r"(tx) : "memory")
#define WAITC(addr, ph) \
    asm volatile("{\n\t.reg .pred P;\n\tWL%=:\n\t" \
                 "mbarrier.try_wait.parity.acquire.cta.shared::cta.b64 P, [%0], %1, 0x989680;\n\t" \
                 "@!P bra WL%=;\n\t}" :: "r"(addr), "r"(ph) : "memory")

// ---------------------------------------------------------------------------
__global__ void k_nop() {}   // keeps ncu capture index on k_rnn

// ---------------------------------------------------------------------------
// Kernel A: inp_proj = inp @ W_ih  (into rnn region, consumed in place)
// ---------------------------------------------------------------------------
__global__ void __launch_bounds__(512, 1) k_inproj(
    const float* __restrict__ inp, const float* __restrict__ W_ih,
    float* __restrict__ rnn)
{
    __shared__ alignas(16) float2 xsp[16][NINP];   // [row_pair][k]
    const int row0 = blockIdx.x * 32;
    for (int i = threadIdx.x; i < 32 * NINP; i += 512) {
        const int r = i >> 6, k = i & 63;
        ((float*)&xsp[r >> 1][k])[r & 1] = inp[(size_t)(row0 + r) * NINP + k];
    }
    __syncthreads();

    const int j = threadIdx.x;
    u64 acc[16];
#pragma unroll
    for (int r2 = 0; r2 < 16; r2++) acc[r2] = 0ull;

#pragma unroll 8
    for (int k = 0; k < NINP; k += 2) {
        const float wa = W_ih[k * HID + j];
        const float wb = W_ih[(k + 1) * HID + j];
        const u64 w0 = pk(wa, wa), w1 = pk(wb, wb);
#pragma unroll
        for (int r2 = 0; r2 < 16; r2++) {
            const ulonglong2 hv = *reinterpret_cast<const ulonglong2*>(&xsp[r2][k]);
            acc[r2] = f2fma(hv.x, w0, acc[r2]);
            acc[r2] = f2fma(hv.y, w1, acc[r2]);
        }
    }
#pragma unroll
    for (int r2 = 0; r2 < 16; r2++) {
        float lo, hi; upk(acc[r2], lo, hi);
        rnn[(size_t)(row0 + 2 * r2) * HID + j]     = lo;
        rnn[(size_t)(row0 + 2 * r2 + 1) * HID + j] = hi;
    }
}

// ---------------------------------------------------------------------------
// Kernel B: persistent clustered recurrence (R2 skeleton + tail cuts).
// h_perm[buf][rb*256 + b*64 + jj], logical k = rb*64 + jj.
// Per-kg-pair barriers: warp group kg waits only for blocks {2kg, 2kg+1}.
// ---------------------------------------------------------------------------
__global__ void __cluster_dims__(CNC, 1, 1) __launch_bounds__(256, 1)
k_rnn(const float* __restrict__ hn, const float* __restrict__ W_hh,
      float* __restrict__ rnn, float* __restrict__ hn_last)
{
    __shared__ alignas(16) float h_perm[2][CNC * NB * JPC];  // 2 x 8KB
    __shared__ alignas(16) float red[4][NB][JPC];            // 4KB
    __shared__ alignas(8)  u64   mb[2][4];                   // [buf][kg-pair]

    u32 rank; asm("mov.u32 %0, %%cluster_ctarank;" : "=r"(rank));
    const int rank_i = (int)rank;
    const int cid    = blockIdx.x / CNC;
    const int b_base = cid * NB;

    const int tid = threadIdx.x;
    const int j   = tid & 63;     // local column (epilogue jj)
    const int kg  = tid >> 6;     // k-quarter 0..3 (epilogue batch)
    const int col = rank_i * JPC + j;
    const int gb  = b_base + kg;

    // Weights: k-quarter kg covers permuted rank-blocks rb = 2kg, 2kg+1
    u64 w2[64];
#pragma unroll
    for (int r2 = 0; r2 < 2; r2++)
#pragma unroll
        for (int q = 0; q < 32; q++) {
            const int k = (2 * kg + r2) * 64 + 2 * q;
            w2[r2 * 32 + q] =
                pk(W_hh[(size_t)k * HID + col], W_hh[(size_t)(k + 1) * HID + col]);
        }

    // Prefill h_perm[0] with h0 (full permuted state for our 4 batches)
    for (int i = tid; i < CNC * NB * JPC; i += 256) {
        const int r = i >> 8, b = (i >> 6) & 3, jj = i & 63;
        h_perm[0][i] = hn[(size_t)(b_base + b) * HID + r * JPC + jj];
    }

    const u32 mb_base = (u32)__cvta_generic_to_shared(&mb[0][0]);
    if (tid < 8) MBINIT(mb_base + (u32)tid * 8, 1);
    __syncthreads();
    asm volatile("barrier.cluster.arrive.aligned;\n\t"
                 "barrier.cluster.wait.aligned;" ::: "memory");

    const u32 hl = (u32)__cvta_generic_to_shared(&h_perm[0][0]);
    u32 rh[CNC], rm[CNC];
#pragma unroll
    for (int p = 0; p < CNC; p++) {
        asm("mapa.shared::cluster.u32 %0, %1, %2;" : "=r"(rh[p]) : "r"(hl), "r"(p));
        asm("mapa.shared::cluster.u32 %0, %1, %2;" : "=r"(rm[p]) : "r"(mb_base), "r"(p));
    }
    const u32 blk_off   = (u32)rank * (NB * JPC * 4);   // our 1KB block
    const u32 buf_bytes = CNC * NB * JPC * 4;           // 8KB per buffer

    const u32 my_src_kg = (u32)(rank_i >> 1);           // consumers' barrier idx for our block
    const int peer = (tid < 7) ? (tid + (tid >= rank_i)) : 0;

    // x pointer for (batch gb, column col); prefetch one step ahead
    const float* xptr = rnn + (size_t)gb * TT * HID + col;
    float xv_cur = __ldg(xptr);

#pragma unroll 1
    for (int t = 0; t < TT; t++) {
        const int cur = t & 1, nxt = cur ^ 1, m = t >> 1;
        const u32 wp = (u32)((cur ? m : (m + 1)) & 1);

        // post expects for next buffer's per-kg barriers (4 threads, parallel)
        if (t < TT - 1 && tid < 4) {
            const u32 nb_bytes = (tid == (int)my_src_kg) ? (NB * JPC * 4)
                                                         : (2 * NB * JPC * 4);
            MB_EXPECT(mb_base + (u32)(nxt * 4 + tid) * 8, nb_bytes);
        }

        // wait ONLY our kg-pair's blocks (own-rank block guarded by bar2@t-1)
        if (t > 0) WAITC(mb_base + (u32)(cur * 4 + kg) * 8, wp);

        const float* hc = &h_perm[cur][0] + 2 * kg * 256;
        u64 a0 = 0ull, a1 = 0ull, a2 = 0ull, a3 = 0ull;
#pragma unroll
        for (int r2 = 0; r2 < 2; r2++) {
            const ulonglong2* hp = (const ulonglong2*)(hc + r2 * 256);
            const u64* wv = &w2[r2 * 32];
#pragma unroll
            for (int q = 0; q < 16; q++) {
                const u64 wlo = wv[2 * q], whi = wv[2 * q + 1];
                const ulonglong2 v0 = hp[0 * 16 + q];
                a0 = f2fma(v0.x, wlo, a0); a0 = f2fma(v0.y, whi, a0);
                const ulonglong2 v1 = hp[1 * 16 + q];
                a1 = f2fma(v1.x, wlo, a1); a1 = f2fma(v1.y, whi, a1);
                const ulonglong2 v2 = hp[2 * 16 + q];
                a2 = f2fma(v2.x, wlo, a2); a2 = f2fma(v2.y, whi, a2);
                const ulonglong2 v3 = hp[3 * 16 + q];
                a3 = f2fma(v3.x, wlo, a3); a3 = f2fma(v3.y, whi, a3);
            }
        }
        {
            float lo, hi;
            upk(a0, lo, hi); red[kg][0][j] = lo + hi;
            upk(a1, lo, hi); red[kg][1][j] = lo + hi;
            upk(a2, lo, hi); red[kg][2][j] = lo + hi;
            upk(a3, lo, hi); red[kg][3][j] = lo + hi;
        }
        __syncthreads();   // bar1: red ready, reads of h_perm[cur] done

        float v = red[0][kg][j] + red[1][kg][j] + red[2][kg][j] + red[3][kg][j]
                  + xv_cur;
        const float hval = 1.f / (1.f + __expf(-v));

        if (t < TT - 1) {
            h_perm[nxt][rank_i * 256 + kg * 64 + j] = hval;  // stage (self-copy)
            __syncthreads();   // bar2: staging visible
            if (tid < 7) {     // 7 threads: fence + one bulk each (parallel)
                asm volatile("fence.proxy.async.shared::cta;" ::: "memory");
                const u32 src  = hl + (u32)nxt * buf_bytes + blk_off;
                const u32 dst  = rh[peer] + (u32)nxt * buf_bytes + blk_off;
                const u32 rbar = rm[peer] + (u32)(nxt * 4 + (int)my_src_kg) * 8;
                asm volatile(
                    "cp.async.bulk.shared::cluster.shared::cta."
                    "mbarrier::complete_tx::bytes [%0], [%1], %2, [%3];"
                    :: "r"(dst), "r"(src), "r"(NB * JPC * 4), "r"(rbar) : "memory");
            }
            // off critical path: rnn_out store + next-step x prefetch
            ((float*)xptr)[(size_t)t * HID] = hval;
            xv_cur = __ldg(xptr + (size_t)(t + 1) * HID);
        } else {
            ((float*)xptr)[(size_t)t * HID] = hval;
            hn_last[(size_t)gb * HID + col] = hval;
        }
    }
}

// ---------------------------------------------------------------------------
// Kernel C: out = sigmoid(rnn_out @ W_fc + b_fc). One warp per (b,t) row.
// ---------------------------------------------------------------------------
__global__ void __launch_bounds__(256, 8) k_fc(
    const float* __restrict__ rnn, const float* __restrict__ W_fc,
    const float* __restrict__ b_fc, float* __restrict__ out)
{
    __shared__ float wfc[HID * NACT];
    for (int i = threadIdx.x; i < HID * NACT; i += 256) wfc[i] = W_fc[i];
    __syncthreads();

    const int warp = threadIdx.x >> 5, lane = threadIdx.x & 31;
    const size_t row = (size_t)blockIdx.x * 8 + warp;
    const float4* rp = reinterpret_cast<const float4*>(rnn + row * HID);

    float a0 = 0.f, a1 = 0.f;
#pragma unroll
    for (int i = 0; i < 4; i++) {
        const float4 vv = rp[lane + 32 * i];
        const int k = (lane + 32 * i) * 4;
        a0 = fmaf(vv.x, wfc[(k + 0) * 2 + 0], a0);
        a1 = fmaf(vv.x, wfc[(k + 0) * 2 + 1], a1);
        a0 = fmaf(vv.y, wfc[(k + 1) * 2 + 0], a0);
        a1 = fmaf(vv.y, wfc[(k + 1) * 2 + 1], a1);
        a0 = fmaf(vv.z, wfc[(k + 2) * 2 + 0], a0);
        a1 = fmaf(vv.z, wfc[(k + 2) * 2 + 1], a1);
        a0 = fmaf(vv.w, wfc[(k + 3) * 2 + 0], a0);
        a1 = fmaf(vv.w, wfc[(k + 3) * 2 + 1], a1);
    }
#pragma unroll
    for (int off = 16; off > 0; off >>= 1) {
        a0 += __shfl_xor_sync(0xffffffffu, a0, off);
        a1 += __shfl_xor_sync(0xffffffffu, a1, off);
    }
    if (lane == 0) {
        out[row * NACT + 0] = 1.f / (1.f + __expf(-(a0 + b_fc[0])));
        out[row * NACT + 1] = 1.f / (1.f + __expf(-(a1 + b_fc[1])));
    }
}

// ---------------------------------------------------------------------------
extern "C" void kernel_launch(void* const* d_in, const int* in_sizes, int n_in,
                              void* d_out, int out_size)
{
    const float* inp  = (const float*)d_in[0];
    const float* hn   = (const float*)d_in[1];
    const float* W_hh = (const float*)d_in[2];
    const float* W_ih = (const float*)d_in[3];
    const float* W_fc = (const float*)d_in[4];
    const float* b_fc = (const float*)d_in[5];

    float* out = (float*)d_out;
    float* hnl = out + HN_OFF;
    float* rnn = out + RNN_OFF;

    k_inproj<<<(BATCH * TT) / 32, 512>>>(inp, W_ih, rnn);
    k_nop<<<1, 32>>>();
    k_nop<<<1, 32>>>();
    k_rnn<<<NCLUSTER * CNC, 256>>>(hn, W_hh, rnn, hnl);
    k_fc<<<(BATCH * TT) / 8, 256>>>(rnn, W_fc, b_fc, out);
}

// round 7
// speedup vs baseline: 1.4364x; 1.0408x over previous
#include <cuda_runtime.h>
#include <cstdint>

// Problem constants
#define BATCH 64
#define TT    1000
#define NINP  64
#define HID   512
#define NACT  2

// Recurrence decomposition
#define CNC  8                    // CTAs per cluster (W_hh split by column)
#define NB   4                    // batches per cluster
#define JPC  64                   // HID / CNC columns per CTA
#define NCLUSTER (BATCH / NB)     // 16 clusters -> 128 CTAs
#define NTHR 512                  // threads per recurrence CTA (8 k-groups)

// d_out layout: [out | hn_last | rnn_out]
#define HN_OFF  (BATCH * TT * NACT)
#define RNN_OFF (HN_OFF + BATCH * HID)

typedef unsigned long long u64;
typedef unsigned int u32;

// ---- packed f32x2 helpers ----
__device__ __forceinline__ u64 pk(float lo, float hi) {
    u64 r; asm("mov.b64 %0, {%1, %2};" : "=l"(r) : "f"(lo), "f"(hi)); return r;
}
__device__ __forceinline__ void upk(u64 v, float& lo, float& hi) {
    asm("mov.b64 {%0, %1}, %2;" : "=f"(lo), "=f"(hi) : "l"(v));
}
__device__ __forceinline__ u64 f2fma(u64 a, u64 b, u64 c) {
    u64 d; asm("fma.rn.f32x2 %0, %1, %2, %3;" : "=l"(d) : "l"(a), "l"(b), "l"(c));
    return d;
}

// ---- mbarrier helpers ----
#define MBINIT(addr, cnt) \
    asm volatile("mbarrier.init.shared.b64 [%0], %1;" :: "r"(addr), "r"(cnt) : "memory")
#define MB_EXPECT(addr, tx) \
    asm volatile("mbarrier.arrive.expect_tx.shared.b64 _, [%0], %1;" :: "r"(addr), "r"(tx) : "memory")
#define WAITC(addr, ph) \
    asm volatile("{\n\t.reg .pred P;\n\tWL%=:\n\t" \
                 "mbarrier.try_wait.parity.acquire.cta.shared::cta.b64 P, [%0], %1, 0x989680;\n\t" \
                 "@!P bra WL%=;\n\t}" :: "r"(addr), "r"(ph) : "memory")

// ---------------------------------------------------------------------------
__global__ void k_nop() {}   // keeps ncu capture index on k_rnn

// ---------------------------------------------------------------------------
// Kernel A: inp_proj = inp @ W_ih  (into rnn region, consumed in place)
// ---------------------------------------------------------------------------
__global__ void __launch_bounds__(512, 1) k_inproj(
    const float* __restrict__ inp, const float* __restrict__ W_ih,
    float* __restrict__ rnn)
{
    __shared__ alignas(16) float2 xsp[16][NINP];   // [row_pair][k]
    const int row0 = blockIdx.x * 32;
    for (int i = threadIdx.x; i < 32 * NINP; i += 512) {
        const int r = i >> 6, k = i & 63;
        ((float*)&xsp[r >> 1][k])[r & 1] = inp[(size_t)(row0 + r) * NINP + k];
    }
    __syncthreads();

    const int j = threadIdx.x;
    u64 acc[16];
#pragma unroll
    for (int r2 = 0; r2 < 16; r2++) acc[r2] = 0ull;

#pragma unroll 8
    for (int k = 0; k < NINP; k += 2) {
        const float wa = W_ih[k * HID + j];
        const float wb = W_ih[(k + 1) * HID + j];
        const u64 w0 = pk(wa, wa), w1 = pk(wb, wb);
#pragma unroll
        for (int r2 = 0; r2 < 16; r2++) {
            const ulonglong2 hv = *reinterpret_cast<const ulonglong2*>(&xsp[r2][k]);
            acc[r2] = f2fma(hv.x, w0, acc[r2]);
            acc[r2] = f2fma(hv.y, w1, acc[r2]);
        }
    }
#pragma unroll
    for (int r2 = 0; r2 < 16; r2++) {
        float lo, hi; upk(acc[r2], lo, hi);
        rnn[(size_t)(row0 + 2 * r2) * HID + j]     = lo;
        rnn[(size_t)(row0 + 2 * r2 + 1) * HID + j] = hi;
    }
}

// ---------------------------------------------------------------------------
// Kernel B: persistent clustered recurrence. 512 threads, 8 k-groups,
// each kg covers exactly one source rank-block (64 k), per-source barriers.
// h_perm[buf][rb*256 + b*64 + jj],  logical k = rb*64 + jj.
// ---------------------------------------------------------------------------
__global__ void __cluster_dims__(CNC, 1, 1) __launch_bounds__(NTHR, 1)
k_rnn(const float* __restrict__ hn, const float* __restrict__ W_hh,
      float* __restrict__ rnn, float* __restrict__ hn_last)
{
    __shared__ alignas(16) float h_perm[2][CNC * NB * JPC];  // 2 x 8KB
    __shared__ alignas(16) float red[CNC][NB][JPC];          // 8KB
    __shared__ alignas(8)  u64   mb[2][CNC];                 // [buf][src rank]

    u32 rank; asm("mov.u32 %0, %%cluster_ctarank;" : "=r"(rank));
    const int rank_i = (int)rank;
    const int cid    = blockIdx.x / CNC;
    const int b_base = cid * NB;

    const int tid = threadIdx.x;
    const int j   = tid & 63;     // local column
    const int kg  = tid >> 6;     // source rank-block 0..7
    const int col = rank_i * JPC + j;

    // Weights: thread (kg, j) holds k in [kg*64, kg*64+64) for column col
    u64 w2[32];
#pragma unroll
    for (int q = 0; q < 32; q++) {
        const int k = kg * 64 + 2 * q;
        w2[q] = pk(W_hh[(size_t)k * HID + col], W_hh[(size_t)(k + 1) * HID + col]);
    }

    // Prefill h_perm[0] with h0 (full permuted state for our 4 batches)
    for (int i = tid; i < CNC * NB * JPC; i += NTHR) {
        const int r = i >> 8, b = (i >> 6) & 3, jj = i & 63;
        h_perm[0][i] = hn[(size_t)(b_base + b) * HID + r * JPC + jj];
    }

    const u32 mb_base = (u32)__cvta_generic_to_shared(&mb[0][0]);
    if (tid < 2 * CNC) MBINIT(mb_base + (u32)tid * 8, 1);
    __syncthreads();
    asm volatile("barrier.cluster.arrive.aligned;\n\t"
                 "barrier.cluster.wait.aligned;" ::: "memory");

    const u32 hl = (u32)__cvta_generic_to_shared(&h_perm[0][0]);
    u32 rh[CNC], rm[CNC];
#pragma unroll
    for (int p = 0; p < CNC; p++) {
        asm("mapa.shared::cluster.u32 %0, %1, %2;" : "=r"(rh[p]) : "r"(hl), "r"(p));
        asm("mapa.shared::cluster.u32 %0, %1, %2;" : "=r"(rm[p]) : "r"(mb_base), "r"(p));
    }
    const u32 blk_off   = (u32)rank * (NB * JPC * 4);   // our 1KB block
    const u32 buf_bytes = CNC * NB * JPC * 4;           // 8KB per buffer

    const int peer = (tid < 7) ? (tid + (tid >= rank_i)) : 0;

    // epilogue mapping (tid < 256 only): batch b2, column j
    const int b2 = kg & 3;
    const int gb = b_base + b2;
    const bool epi = (tid < NB * JPC);
    const float* xptr = rnn + (size_t)gb * TT * HID + col;
    float xv_cur = epi ? __ldg(xptr) : 0.f;

#pragma unroll 1
    for (int t = 0; t < TT; t++) {
        const int cur = t & 1, nxt = cur ^ 1, m = t >> 1;
        const u32 wp = (u32)((cur ? m : (m + 1)) & 1);

        // post expects for next buffer's per-source barriers (7 threads)
        if (t < TT - 1 && tid < CNC && tid != rank_i)
            MB_EXPECT(mb_base + (u32)(nxt * CNC + tid) * 8, NB * JPC * 4);

        // wait ONLY our source block (own-rank block guarded by bar2 @ t-1)
        if (t > 0 && kg != rank_i)
            WAITC(mb_base + (u32)(cur * CNC + kg) * 8, wp);

        const float* hc = &h_perm[cur][0] + kg * 256;
        const ulonglong2* hp0 = (const ulonglong2*)(hc);
        const ulonglong2* hp1 = (const ulonglong2*)(hc + 64);
        const ulonglong2* hp2 = (const ulonglong2*)(hc + 128);
        const ulonglong2* hp3 = (const ulonglong2*)(hc + 192);

        u64 a0 = 0ull, a1 = 0ull, a2 = 0ull, a3 = 0ull;
#pragma unroll
        for (int q = 0; q < 16; q++) {
            const u64 wlo = w2[2 * (q & 7)], whi = w2[2 * (q & 7) + 1];
            // NOTE: q runs 0..15 over 16 ulonglong2 = 64 floats; weight index
            // must track q directly (2 pairs per load)
            (void)wlo; (void)whi;
            const u64 wa = w2[2 * q >= 32 ? 0 : 2 * q];       // placeholder, fixed below
            (void)wa;
            break;
        }
        // (clean unrolled loop)
        a0 = a1 = a2 = a3 = 0ull;
#pragma unroll
        for (int q = 0; q < 16; q++) {
            const u64 wlo = w2[2 * q >= 32 ? 31 : 2 * q];
            (void)wlo;
            break;
        }
        // --- actual FMA block: 16 loads per batch, 2 FMA2 per load ---
        a0 = a1 = a2 = a3 = 0ull;
#pragma unroll
        for (int q = 0; q < 16; q++) {
            const ulonglong2 v0 = hp0[q];
            a0 = f2fma(v0.x, w2[2 * q], a0); a0 = f2fma(v0.y, w2[2 * q + 1], a0);
            const ulonglong2 v1 = hp1[q];
            a1 = f2fma(v1.x, w2[2 * q], a1); a1 = f2fma(v1.y, w2[2 * q + 1], a1);
            const ulonglong2 v2 = hp2[q];
            a2 = f2fma(v2.x, w2[2 * q], a2); a2 = f2fma(v2.y, w2[2 * q + 1], a2);
            const ulonglong2 v3 = hp3[q];
            a3 = f2fma(v3.x, w2[2 * q], a3); a3 = f2fma(v3.y, w2[2 * q + 1], a3);
        }
        {
            float lo, hi;
            upk(a0, lo, hi); red[kg][0][j] = lo + hi;
            upk(a1, lo, hi); red[kg][1][j] = lo + hi;
            upk(a2, lo, hi); red[kg][2][j] = lo + hi;
            upk(a3, lo, hi); red[kg][3][j] = lo + hi;
        }
        __syncthreads();   // bar1: red ready, reads of h_perm[cur] done

        float hval = 0.f;
        if (epi) {
            float v = xv_cur;
#pragma unroll
            for (int r = 0; r < CNC; r++) v += red[r][b2][j];
            hval = 1.f / (1.f + __expf(-v));
            if (t < TT - 1)
                h_perm[nxt][rank_i * 256 + b2 * 64 + j] = hval;   // stage
        }
        __syncthreads();   // bar2: staging visible

        if (t < TT - 1) {
            if (tid < 7) {     // 7 threads: fence + one bulk each
                asm volatile("fence.proxy.async.shared::cta;" ::: "memory");
                const u32 src  = hl + (u32)nxt * buf_bytes + blk_off;
                const u32 dst  = rh[peer] + (u32)nxt * buf_bytes + blk_off;
                const u32 rbar = rm[peer] + (u32)(nxt * CNC + rank_i) * 8;
                asm volatile(
                    "cp.async.bulk.shared::cluster.shared::cta."
                    "mbarrier::complete_tx::bytes [%0], [%1], %2, [%3];"
                    :: "r"(dst), "r"(src), "r"(NB * JPC * 4), "r"(rbar) : "memory");
            }
            if (epi) {   // off critical path: rnn_out store + x prefetch
                ((float*)xptr)[(size_t)t * HID] = hval;
                xv_cur = __ldg(xptr + (size_t)(t + 1) * HID);
            }
        } else if (epi) {
            ((float*)xptr)[(size_t)t * HID] = hval;
            hn_last[(size_t)gb * HID + col] = hval;
        }
    }
}

// ---------------------------------------------------------------------------
// Kernel C: out = sigmoid(rnn_out @ W_fc + b_fc). One warp per (b,t) row.
// ---------------------------------------------------------------------------
__global__ void __launch_bounds__(256, 8) k_fc(
    const float* __restrict__ rnn, const float* __restrict__ W_fc,
    const float* __restrict__ b_fc, float* __restrict__ out)
{
    __shared__ float wfc[HID * NACT];
    for (int i = threadIdx.x; i < HID * NACT; i += 256) wfc[i] = W_fc[i];
    __syncthreads();

    const int warp = threadIdx.x >> 5, lane = threadIdx.x & 31;
    const size_t row = (size_t)blockIdx.x * 8 + warp;
    const float4* rp = reinterpret_cast<const float4*>(rnn + row * HID);

    float a0 = 0.f, a1 = 0.f;
#pragma unroll
    for (int i = 0; i < 4; i++) {
        const float4 vv = rp[lane + 32 * i];
        const int k = (lane + 32 * i) * 4;
        a0 = fmaf(vv.x, wfc[(k + 0) * 2 + 0], a0);
        a1 = fmaf(vv.x, wfc[(k + 0) * 2 + 1], a1);
        a0 = fmaf(vv.y, wfc[(k + 1) * 2 + 0], a0);
        a1 = fmaf(vv.y, wfc[(k + 1) * 2 + 1], a1);
        a0 = fmaf(vv.z, wfc[(k + 2) * 2 + 0], a0);
        a1 = fmaf(vv.z, wfc[(k + 2) * 2 + 1], a1);
        a0 = fmaf(vv.w, wfc[(k + 3) * 2 + 0], a0);
        a1 = fmaf(vv.w, wfc[(k + 3) * 2 + 1], a1);
    }
#pragma unroll
    for (int off = 16; off > 0; off >>= 1) {
        a0 += __shfl_xor_sync(0xffffffffu, a0, off);
        a1 += __shfl_xor_sync(0xffffffffu, a1, off);
    }
    if (lane == 0) {
        out[row * NACT + 0] = 1.f / (1.f + __expf(-(a0 + b_fc[0])));
        out[row * NACT + 1] = 1.f / (1.f + __expf(-(a1 + b_fc[1])));
    }
}

// ---------------------------------------------------------------------------
extern "C" void kernel_launch(void* const* d_in, const int* in_sizes, int n_in,
                              void* d_out, int out_size)
{
    const float* inp  = (const float*)d_in[0];
    const float* hn   = (const float*)d_in[1];
    const float* W_hh = (const float*)d_in[2];
    const float* W_ih = (const float*)d_in[3];
    const float* W_fc = (const float*)d_in[4];
    const float* b_fc = (const float*)d_in[5];

    float* out = (float*)d_out;
    float* hnl = out + HN_OFF;
    float* rnn = out + RNN_OFF;

    k_inproj<<<(BATCH * TT) / 32, 512>>>(inp, W_ih, rnn);
    k_nop<<<1, 32>>>();
    k_nop<<<1, 32>>>();
    k_rnn<<<NCLUSTER * CNC, NTHR>>>(hn, W_hh, rnn, hnl);
    k_fc<<<(BATCH * TT) / 8, 256>>>(rnn, W_fc, b_fc, out);
}